// round 2
// baseline (speedup 1.0000x reference)
#include <cuda_runtime.h>
#include <cstddef>

#define B_ROWS 4096
#define D_INF  128
#define H_DIM  512
#define D_OUT  256
#define M_CON  64

#define SIGMA_F 1.0f
#define OMEGA_F 1.7f
#define INV_F   0.5f   // 1/(1+SIGMA)

__device__ float g_Mop[M_CON * D_OUT];
__device__ float g_h1[B_ROWS * H_DIM];
__device__ float g_h2[B_ROWS * H_DIM];
__device__ float g_y0[B_ROWS * D_OUT];

// ---------------------------------------------------------------------------
// Setup: Mop = inv(A A^T) @ A.   A is [64, 256]. Single CTA, 256 threads.
// Gram is SPD and well conditioned -> Gauss-Jordan without pivoting is fine.
// ---------------------------------------------------------------------------
__global__ void __launch_bounds__(256) setup_kernel(const float* __restrict__ A,
                                                    float* __restrict__ Mop) {
    __shared__ float Gs[64][65];
    __shared__ float Ks[64][65];
    __shared__ float fcol[64];
    int tid = threadIdx.x;

    // Gram = A A^T
    for (int idx = tid; idx < 64 * 64; idx += 256) {
        int i = idx >> 6, j = idx & 63;
        float s = 0.f;
        const float* ai = A + (size_t)i * D_OUT;
        const float* aj = A + (size_t)j * D_OUT;
        #pragma unroll 8
        for (int d = 0; d < D_OUT; d++) s += ai[d] * aj[d];
        Gs[i][j] = s;
        Ks[i][j] = (i == j) ? 1.f : 0.f;
    }
    __syncthreads();

    for (int k = 0; k < 64; k++) {
        float pinv = 1.f / Gs[k][k];
        if (tid < 64) fcol[tid] = Gs[tid][k];
        __syncthreads();
        if (tid < 64) {
            Gs[k][tid] *= pinv;
            Ks[k][tid] *= pinv;
        }
        __syncthreads();
        for (int idx = tid; idx < 64 * 64; idx += 256) {
            int i = idx >> 6, j = idx & 63;
            if (i != k) {
                float f = fcol[i];
                Gs[i][j] -= f * Gs[k][j];
                Ks[i][j] -= f * Ks[k][j];
            }
        }
        __syncthreads();
    }

    // Mop = Ks @ A   [64, 256]
    for (int idx = tid; idx < 64 * D_OUT; idx += 256) {
        int m = idx >> 8, d = idx & 255;
        float s = 0.f;
        #pragma unroll 8
        for (int j = 0; j < 64; j++) s += Ks[m][j] * A[(size_t)j * D_OUT + d];
        Mop[(size_t)m * D_OUT + d] = s;
    }
}

// ---------------------------------------------------------------------------
// Trunk GEMM: C[B,N] = act(X[B,K] @ W[K,N] + b).  64x64 tile, 256 threads,
// 4x4 micro-tile, K-step 16.  B,N multiples of 64; K multiple of 16.
// ---------------------------------------------------------------------------
__global__ void __launch_bounds__(256) gemm_kernel(const float* __restrict__ X,
                                                   const float* __restrict__ W,
                                                   const float* __restrict__ bias,
                                                   float* __restrict__ C,
                                                   int K, int N, int do_relu) {
    __shared__ float Xs[16][68];   // transposed: Xs[k][m]
    __shared__ float Ws[16][64];

    int tid = threadIdx.x;
    int cb = blockIdx.x * 64;
    int rb = blockIdx.y * 64;
    int ty = tid >> 4, tx = tid & 15;

    float acc[4][4];
    #pragma unroll
    for (int i = 0; i < 4; i++)
        #pragma unroll
        for (int j = 0; j < 4; j++) acc[i][j] = 0.f;

    int xr = tid >> 2;            // 0..63
    int xc = (tid & 3) * 4;       // 0,4,8,12
    int wr = tid >> 4;            // 0..15
    int wc = (tid & 15) * 4;      // 0..60

    for (int k0 = 0; k0 < K; k0 += 16) {
        float4 xv = *(const float4*)(X + (size_t)(rb + xr) * K + k0 + xc);
        Xs[xc + 0][xr] = xv.x;
        Xs[xc + 1][xr] = xv.y;
        Xs[xc + 2][xr] = xv.z;
        Xs[xc + 3][xr] = xv.w;
        float4 wv = *(const float4*)(W + (size_t)(k0 + wr) * N + cb + wc);
        *(float4*)&Ws[wr][wc] = wv;
        __syncthreads();

        #pragma unroll
        for (int kk = 0; kk < 16; kk++) {
            float a0 = Xs[kk][ty * 4 + 0];
            float a1 = Xs[kk][ty * 4 + 1];
            float a2 = Xs[kk][ty * 4 + 2];
            float a3 = Xs[kk][ty * 4 + 3];
            float4 b = *(float4*)&Ws[kk][tx * 4];
            acc[0][0] += a0 * b.x; acc[0][1] += a0 * b.y; acc[0][2] += a0 * b.z; acc[0][3] += a0 * b.w;
            acc[1][0] += a1 * b.x; acc[1][1] += a1 * b.y; acc[1][2] += a1 * b.z; acc[1][3] += a1 * b.w;
            acc[2][0] += a2 * b.x; acc[2][1] += a2 * b.y; acc[2][2] += a2 * b.z; acc[2][3] += a2 * b.w;
            acc[3][0] += a3 * b.x; acc[3][1] += a3 * b.y; acc[3][2] += a3 * b.z; acc[3][3] += a3 * b.w;
        }
        __syncthreads();
    }

    float4 bv = *(const float4*)(bias + cb + tx * 4);
    #pragma unroll
    for (int i = 0; i < 4; i++) {
        int row = rb + ty * 4 + i;
        float4 o;
        o.x = acc[i][0] + bv.x;
        o.y = acc[i][1] + bv.y;
        o.z = acc[i][2] + bv.z;
        o.w = acc[i][3] + bv.w;
        if (do_relu) {
            o.x = fmaxf(o.x, 0.f); o.y = fmaxf(o.y, 0.f);
            o.z = fmaxf(o.z, 0.f); o.w = fmaxf(o.w, 0.f);
        }
        *(float4*)(C + (size_t)row * N + cb + tx * 4) = o;
    }
}

// ---------------------------------------------------------------------------
// Solver: persistent per-row-block Douglas-Rachford.
// CTA = 256 threads = 8 warps; 32 rows per CTA.
// warp w: rows w*4 + (lane&3); lane>>2 = d-chunk (8 chunks x 32 floats).
// A [64x256] and Mop [64x256] in dynamic shared. All state in registers.
// ---------------------------------------------------------------------------
__global__ void __launch_bounds__(256, 1) solve_kernel(
    const float* __restrict__ A, const float* __restrict__ bcon,
    const float* __restrict__ y0g, const float* __restrict__ Mop,
    const int* __restrict__ p_niter, float* __restrict__ out) {
    extern __shared__ float sm[];
    float* As = sm;                       // 64*256
    float* Ms = sm + 64 * 256;            // 64*256
    float* Bs = sm + 2 * 64 * 256;        // 32*68 (bcon block, padded)

    int tid = threadIdx.x;
    int rb = blockIdx.x * 32;

    // cooperative load A and Mop (4096 float4 each)
    {
        const float4* A4  = (const float4*)A;
        const float4* M4  = (const float4*)Mop;
        float4* As4s = (float4*)As;
        float4* Ms4s = (float4*)Ms;
        #pragma unroll
        for (int i = 0; i < 16; i++) {
            As4s[tid + i * 256] = A4[tid + i * 256];
            Ms4s[tid + i * 256] = M4[tid + i * 256];
        }
        // bcon block: 32 rows x 64
        const float4* bc4 = (const float4*)(bcon + (size_t)rb * M_CON);
        #pragma unroll
        for (int i = 0; i < 2; i++) {
            int fl = tid + i * 256;        // 0..511
            float4 v = bc4[fl];
            int r = fl >> 4;               // row 0..31
            int c = (fl & 15) * 4;
            Bs[r * 68 + c + 0] = v.x;
            Bs[r * 68 + c + 1] = v.y;
            Bs[r * 68 + c + 2] = v.z;
            Bs[r * 68 + c + 3] = v.w;
        }
    }
    __syncthreads();

    int lane  = tid & 31;
    int w     = tid >> 5;
    int r4    = lane & 3;
    int chunk = lane >> 2;                 // 0..7
    int row_l = w * 4 + r4;                // 0..31
    int row_g = rb + row_l;
    int cb4   = chunk * 8;                 // float4 base within row

    int qoff[8];
    #pragma unroll
    for (int q = 0; q < 8; q++) qoff[q] = ((q + chunk) & 7);  // bank-conflict-free rotation

    const float4* As4 = (const float4*)As;
    const float4* Ms4 = (const float4*)Ms;

    float y0r[32], zr[32], cr[32], v[32], y[32];

    // load y0 / init z (permuted chunk order, consistent everywhere)
    {
        const float4* yr = (const float4*)(y0g + (size_t)row_g * D_OUT);
        #pragma unroll
        for (int q = 0; q < 8; q++) {
            float4 t = yr[cb4 + qoff[q]];
            y0r[q * 4 + 0] = t.x; y0r[q * 4 + 1] = t.y;
            y0r[q * 4 + 2] = t.z; y0r[q * 4 + 3] = t.w;
            zr[q * 4 + 0] = t.x; zr[q * 4 + 1] = t.y;
            zr[q * 4 + 2] = t.z; zr[q * 4 + 3] = t.w;
        }
    }

    // c = bcon @ Mop  (per-row constant)
    #pragma unroll
    for (int j = 0; j < 32; j++) cr[j] = 0.f;
    #pragma unroll 8
    for (int m = 0; m < 64; m++) {
        float bm = Bs[row_l * 68 + m];
        #pragma unroll
        for (int q = 0; q < 8; q++) {
            float4 ms = Ms4[m * 64 + cb4 + qoff[q]];
            cr[q * 4 + 0] += bm * ms.x;
            cr[q * 4 + 1] += bm * ms.y;
            cr[q * 4 + 2] += bm * ms.z;
            cr[q * 4 + 3] += bm * ms.w;
        }
    }

    int niter = *p_niter;
    for (int it = 0; it < niter; it++) {
        #pragma unroll
        for (int j = 0; j < 32; j++) {
            v[j] = (zr[j] + SIGMA_F * y0r[j]) * INV_F;
            y[j] = v[j] + cr[j];
        }
        // y = v + c - (v A^T) Mop, processed in groups of 8 constraints
        for (int mo = 0; mo < 64; mo += 8) {
            float rg[8];
            #pragma unroll
            for (int mi = 0; mi < 8; mi++) {
                float acc = 0.f;
                #pragma unroll
                for (int q = 0; q < 8; q++) {
                    float4 a = As4[(mo + mi) * 64 + cb4 + qoff[q]];
                    acc += v[q * 4 + 0] * a.x + v[q * 4 + 1] * a.y
                         + v[q * 4 + 2] * a.z + v[q * 4 + 3] * a.w;
                }
                rg[mi] = acc;
            }
            #pragma unroll
            for (int mi = 0; mi < 8; mi++) {
                rg[mi] += __shfl_xor_sync(0xffffffffu, rg[mi], 4);
                rg[mi] += __shfl_xor_sync(0xffffffffu, rg[mi], 8);
                rg[mi] += __shfl_xor_sync(0xffffffffu, rg[mi], 16);
            }
            #pragma unroll
            for (int mi = 0; mi < 8; mi++) {
                float rm = rg[mi];
                #pragma unroll
                for (int q = 0; q < 8; q++) {
                    float4 ms = Ms4[(mo + mi) * 64 + cb4 + qoff[q]];
                    y[q * 4 + 0] -= rm * ms.x;
                    y[q * 4 + 1] -= rm * ms.y;
                    y[q * 4 + 2] -= rm * ms.z;
                    y[q * 4 + 3] -= rm * ms.w;
                }
            }
        }
        #pragma unroll
        for (int j = 0; j < 32; j++) {
            float wv = fmaxf(2.f * y[j] - zr[j], 0.f);
            zr[j] += OMEGA_F * (wv - y[j]);
        }
    }

    float4* orow = (float4*)(out + (size_t)row_g * D_OUT);
    #pragma unroll
    for (int q = 0; q < 8; q++) {
        float4 t;
        t.x = y[q * 4 + 0]; t.y = y[q * 4 + 1];
        t.z = y[q * 4 + 2]; t.w = y[q * 4 + 3];
        orow[cb4 + qoff[q]] = t;
    }
}

// ---------------------------------------------------------------------------
extern "C" void kernel_launch(void* const* d_in, const int* in_sizes, int n_in,
                              void* d_out, int out_size) {
    const float* x    = (const float*)d_in[0];
    const float* bcon = (const float*)d_in[1];
    const float* A    = (const float*)d_in[2];
    const float* W1   = (const float*)d_in[3];
    const float* b1   = (const float*)d_in[4];
    const float* W2   = (const float*)d_in[5];
    const float* b2   = (const float*)d_in[6];
    const float* W3   = (const float*)d_in[7];
    const float* b3   = (const float*)d_in[8];
    const float* Wout = (const float*)d_in[9];
    const float* bout = (const float*)d_in[10];
    const int*   nit  = (const int*)d_in[11];
    float* out = (float*)d_out;

    float *p_Mop, *p_h1, *p_h2, *p_y0;
    cudaGetSymbolAddress((void**)&p_Mop, g_Mop);
    cudaGetSymbolAddress((void**)&p_h1, g_h1);
    cudaGetSymbolAddress((void**)&p_h2, g_h2);
    cudaGetSymbolAddress((void**)&p_y0, g_y0);

    // trunk
    gemm_kernel<<<dim3(H_DIM / 64, B_ROWS / 64), 256>>>(x,    W1,   b1,   p_h1, D_INF, H_DIM, 1);
    gemm_kernel<<<dim3(H_DIM / 64, B_ROWS / 64), 256>>>(p_h1, W2,   b2,   p_h2, H_DIM, H_DIM, 1);
    gemm_kernel<<<dim3(H_DIM / 64, B_ROWS / 64), 256>>>(p_h2, W3,   b3,   p_h1, H_DIM, H_DIM, 1);
    gemm_kernel<<<dim3(D_OUT / 64, B_ROWS / 64), 256>>>(p_h1, Wout, bout, p_y0, H_DIM, D_OUT, 0);

    // projection operator
    setup_kernel<<<1, 256>>>(A, p_Mop);

    // persistent DR solver
    size_t smem = (size_t)(2 * 64 * 256 + 32 * 68) * sizeof(float);
    cudaFuncSetAttribute(solve_kernel, cudaFuncAttributeMaxDynamicSharedMemorySize, (int)smem);
    solve_kernel<<<B_ROWS / 32, 256, smem>>>(A, bcon, p_y0, p_Mop, nit, out);
}

// round 3
// speedup vs baseline: 1.0609x; 1.0609x over previous
#include <cuda_runtime.h>
#include <cstddef>

#define B_ROWS 4096
#define D_INF  128
#define H_DIM  512
#define D_OUT  256
#define M_CON  64

#define SIGMA_F 1.0f
#define OMEGA_F 1.7f
#define INV_F   0.5f   // 1/(1+SIGMA)

typedef unsigned long long u64;

__device__ __forceinline__ u64 ffma2(u64 a, u64 b, u64 c) {
    u64 d; asm("fma.rn.f32x2 %0,%1,%2,%3;" : "=l"(d) : "l"(a), "l"(b), "l"(c)); return d;
}
__device__ __forceinline__ u64 fadd2(u64 a, u64 b) {
    u64 d; asm("add.rn.f32x2 %0,%1,%2;" : "=l"(d) : "l"(a), "l"(b)); return d;
}
__device__ __forceinline__ u64 fmul2(u64 a, u64 b) {
    u64 d; asm("mul.rn.f32x2 %0,%1,%2;" : "=l"(d) : "l"(a), "l"(b)); return d;
}
__device__ __forceinline__ u64 pack2(float x, float y) {
    u64 d; asm("mov.b64 %0,{%1,%2};" : "=l"(d) : "f"(x), "f"(y)); return d;
}
__device__ __forceinline__ void unpack2(u64 v, float& x, float& y) {
    asm("mov.b64 {%0,%1},%2;" : "=f"(x), "=f"(y) : "l"(v));
}

__device__ float g_Mop[M_CON * D_OUT];
__device__ float g_h1[B_ROWS * H_DIM];
__device__ float g_h2[B_ROWS * H_DIM];
__device__ float g_y0[B_ROWS * D_OUT];

// ---------------------------------------------------------------------------
// Setup: Mop = inv(A A^T) @ A.   A is [64, 256]. Single CTA, 256 threads.
// ---------------------------------------------------------------------------
__global__ void __launch_bounds__(256) setup_kernel(const float* __restrict__ A,
                                                    float* __restrict__ Mop) {
    __shared__ float Gs[64][65];
    __shared__ float Ks[64][65];
    __shared__ float fcol[64];
    int tid = threadIdx.x;

    for (int idx = tid; idx < 64 * 64; idx += 256) {
        int i = idx >> 6, j = idx & 63;
        float s = 0.f;
        const float* ai = A + (size_t)i * D_OUT;
        const float* aj = A + (size_t)j * D_OUT;
        #pragma unroll 8
        for (int d = 0; d < D_OUT; d++) s += ai[d] * aj[d];
        Gs[i][j] = s;
        Ks[i][j] = (i == j) ? 1.f : 0.f;
    }
    __syncthreads();

    for (int k = 0; k < 64; k++) {
        float pinv = 1.f / Gs[k][k];
        if (tid < 64) fcol[tid] = Gs[tid][k];
        __syncthreads();
        if (tid < 64) {
            Gs[k][tid] *= pinv;
            Ks[k][tid] *= pinv;
        }
        __syncthreads();
        for (int idx = tid; idx < 64 * 64; idx += 256) {
            int i = idx >> 6, j = idx & 63;
            if (i != k) {
                float f = fcol[i];
                Gs[i][j] -= f * Gs[k][j];
                Ks[i][j] -= f * Ks[k][j];
            }
        }
        __syncthreads();
    }

    for (int idx = tid; idx < 64 * D_OUT; idx += 256) {
        int m = idx >> 8, d = idx & 255;
        float s = 0.f;
        #pragma unroll 8
        for (int j = 0; j < 64; j++) s += Ks[m][j] * A[(size_t)j * D_OUT + d];
        Mop[(size_t)m * D_OUT + d] = s;
    }
}

// ---------------------------------------------------------------------------
// Trunk GEMM: C[B,N] = act(X[B,K] @ W[K,N] + b).  64x64 tile, 256 threads,
// 4x4 micro-tile (cols as 2x f32x2), K-step 16.
// ---------------------------------------------------------------------------
__global__ void __launch_bounds__(256) gemm_kernel(const float* __restrict__ X,
                                                   const float* __restrict__ W,
                                                   const float* __restrict__ bias,
                                                   float* __restrict__ C,
                                                   int K, int N, int do_relu) {
    __shared__ float Xs[16][68];   // transposed: Xs[k][m]
    __shared__ float Ws[16][64];

    int tid = threadIdx.x;
    int cb = blockIdx.x * 64;
    int rb = blockIdx.y * 64;
    int ty = tid >> 4, tx = tid & 15;

    u64 acc[4][2];
    #pragma unroll
    for (int i = 0; i < 4; i++) { acc[i][0] = 0ull; acc[i][1] = 0ull; }

    int xr = tid >> 2;
    int xc = (tid & 3) * 4;
    int wr = tid >> 4;
    int wc = (tid & 15) * 4;

    for (int k0 = 0; k0 < K; k0 += 16) {
        float4 xv = *(const float4*)(X + (size_t)(rb + xr) * K + k0 + xc);
        Xs[xc + 0][xr] = xv.x;
        Xs[xc + 1][xr] = xv.y;
        Xs[xc + 2][xr] = xv.z;
        Xs[xc + 3][xr] = xv.w;
        float4 wv = *(const float4*)(W + (size_t)(k0 + wr) * N + cb + wc);
        *(float4*)&Ws[wr][wc] = wv;
        __syncthreads();

        #pragma unroll
        for (int kk = 0; kk < 16; kk++) {
            ulonglong2 b = *(ulonglong2*)&Ws[kk][tx * 4];
            #pragma unroll
            for (int i = 0; i < 4; i++) {
                float a = Xs[kk][ty * 4 + i];
                u64 a2 = pack2(a, a);
                acc[i][0] = ffma2(a2, b.x, acc[i][0]);
                acc[i][1] = ffma2(a2, b.y, acc[i][1]);
            }
        }
        __syncthreads();
    }

    float4 bv = *(const float4*)(bias + cb + tx * 4);
    #pragma unroll
    for (int i = 0; i < 4; i++) {
        int row = rb + ty * 4 + i;
        float4 o;
        unpack2(acc[i][0], o.x, o.y);
        unpack2(acc[i][1], o.z, o.w);
        o.x += bv.x; o.y += bv.y; o.z += bv.z; o.w += bv.w;
        if (do_relu) {
            o.x = fmaxf(o.x, 0.f); o.y = fmaxf(o.y, 0.f);
            o.z = fmaxf(o.z, 0.f); o.w = fmaxf(o.w, 0.f);
        }
        *(float4*)(C + (size_t)row * N + cb + tx * 4) = o;
    }
}

// ---------------------------------------------------------------------------
// Solver: persistent per-row-block Douglas-Rachford, f32x2 math.
// CTA = 256 threads = 8 warps; 32 rows per CTA.
// warp w: rows w*4 + (lane&3); lane>>2 = d-chunk (8 chunks x 32 floats).
// A [64x256] and Mop [64x256] in dynamic shared, broadcast-friendly layout.
// ---------------------------------------------------------------------------
__global__ void __launch_bounds__(256, 1) solve_kernel(
    const float* __restrict__ A, const float* __restrict__ bcon,
    const float* __restrict__ y0g, const float* __restrict__ Mop,
    const int* __restrict__ p_niter, float* __restrict__ out) {
    extern __shared__ float sm[];
    float* As = sm;                       // 64*256
    float* Ms = sm + 64 * 256;            // 64*256
    float* Bs = sm + 2 * 64 * 256;        // 32*68

    int tid = threadIdx.x;
    int rb = blockIdx.x * 32;

    {
        const float4* A4 = (const float4*)A;
        const float4* M4 = (const float4*)Mop;
        float4* As4s = (float4*)As;
        float4* Ms4s = (float4*)Ms;
        #pragma unroll
        for (int i = 0; i < 16; i++) {
            As4s[tid + i * 256] = A4[tid + i * 256];
            Ms4s[tid + i * 256] = M4[tid + i * 256];
        }
        const float4* bc4 = (const float4*)(bcon + (size_t)rb * M_CON);
        #pragma unroll
        for (int i = 0; i < 2; i++) {
            int fl = tid + i * 256;
            float4 v = bc4[fl];
            int r = fl >> 4;
            int c = (fl & 15) * 4;
            Bs[r * 68 + c + 0] = v.x;
            Bs[r * 68 + c + 1] = v.y;
            Bs[r * 68 + c + 2] = v.z;
            Bs[r * 68 + c + 3] = v.w;
        }
    }
    __syncthreads();

    int lane  = tid & 31;
    int w     = tid >> 5;
    int r4    = lane & 3;
    int chunk = lane >> 2;
    int row_l = w * 4 + r4;
    int row_g = rb + row_l;
    int cb4   = chunk * 8;

    int qoff[8];
    #pragma unroll
    for (int q = 0; q < 8; q++) qoff[q] = ((q + chunk) & 7);

    const ulonglong2* As2 = (const ulonglong2*)As;   // indexed in float4 units
    const ulonglong2* Ms2 = (const ulonglong2*)Ms;

    u64 y0r[16], zr[16], cr[16], vr[16], yv[16];

    {
        const ulonglong2* yr = (const ulonglong2*)(y0g + (size_t)row_g * D_OUT);
        #pragma unroll
        for (int q = 0; q < 8; q++) {
            ulonglong2 t = yr[cb4 + qoff[q]];
            y0r[2 * q]     = t.x;  y0r[2 * q + 1] = t.y;
            zr[2 * q]      = t.x;  zr[2 * q + 1]  = t.y;
        }
    }

    // c = bcon @ Mop
    #pragma unroll
    for (int j = 0; j < 16; j++) cr[j] = 0ull;
    #pragma unroll 8
    for (int m = 0; m < 64; m++) {
        float bm = Bs[row_l * 68 + m];
        u64 bm2 = pack2(bm, bm);
        #pragma unroll
        for (int q = 0; q < 8; q++) {
            ulonglong2 ms = Ms2[m * 64 + cb4 + qoff[q]];
            cr[2 * q]     = ffma2(bm2, ms.x, cr[2 * q]);
            cr[2 * q + 1] = ffma2(bm2, ms.y, cr[2 * q + 1]);
        }
    }

    const u64 half2 = pack2(INV_F, INV_F);
    int niter = *p_niter;

    for (int it = 0; it < niter; it++) {
        #pragma unroll
        for (int j = 0; j < 16; j++) {
            vr[j] = fmul2(fadd2(zr[j], y0r[j]), half2);   // SIGMA = 1
            yv[j] = fadd2(vr[j], cr[j]);
        }
        for (int mo = 0; mo < 64; mo += 8) {
            float rg[8];
            #pragma unroll
            for (int mi = 0; mi < 8; mi++) {
                u64 acc0 = 0ull, acc1 = 0ull;
                #pragma unroll
                for (int q = 0; q < 8; q += 2) {
                    ulonglong2 a0 = As2[(mo + mi) * 64 + cb4 + qoff[q]];
                    ulonglong2 a1 = As2[(mo + mi) * 64 + cb4 + qoff[q + 1]];
                    acc0 = ffma2(vr[2 * q],     a0.x, acc0);
                    acc0 = ffma2(vr[2 * q + 1], a0.y, acc0);
                    acc1 = ffma2(vr[2 * q + 2], a1.x, acc1);
                    acc1 = ffma2(vr[2 * q + 3], a1.y, acc1);
                }
                acc0 = fadd2(acc0, acc1);
                float lo, hi;
                unpack2(acc0, lo, hi);
                rg[mi] = lo + hi;
            }
            #pragma unroll
            for (int mi = 0; mi < 8; mi++) {
                rg[mi] += __shfl_xor_sync(0xffffffffu, rg[mi], 4);
                rg[mi] += __shfl_xor_sync(0xffffffffu, rg[mi], 8);
                rg[mi] += __shfl_xor_sync(0xffffffffu, rg[mi], 16);
            }
            #pragma unroll
            for (int mi = 0; mi < 8; mi++) {
                float nrm = -rg[mi];
                u64 nrm2 = pack2(nrm, nrm);
                #pragma unroll
                for (int q = 0; q < 8; q++) {
                    ulonglong2 ms = Ms2[(mo + mi) * 64 + cb4 + qoff[q]];
                    yv[2 * q]     = ffma2(nrm2, ms.x, yv[2 * q]);
                    yv[2 * q + 1] = ffma2(nrm2, ms.y, yv[2 * q + 1]);
                }
            }
        }
        #pragma unroll
        for (int j = 0; j < 16; j++) {
            float y0f, y1f, z0f, z1f;
            unpack2(yv[j], y0f, y1f);
            unpack2(zr[j], z0f, z1f);
            float w0 = fmaxf(2.f * y0f - z0f, 0.f);
            float w1 = fmaxf(2.f * y1f - z1f, 0.f);
            z0f += OMEGA_F * (w0 - y0f);
            z1f += OMEGA_F * (w1 - y1f);
            zr[j] = pack2(z0f, z1f);
        }
    }

    ulonglong2* orow = (ulonglong2*)(out + (size_t)row_g * D_OUT);
    #pragma unroll
    for (int q = 0; q < 8; q++) {
        ulonglong2 t;
        t.x = yv[2 * q];
        t.y = yv[2 * q + 1];
        orow[cb4 + qoff[q]] = t;
    }
}

// ---------------------------------------------------------------------------
extern "C" void kernel_launch(void* const* d_in, const int* in_sizes, int n_in,
                              void* d_out, int out_size) {
    const float* x    = (const float*)d_in[0];
    const float* bcon = (const float*)d_in[1];
    const float* A    = (const float*)d_in[2];
    const float* W1   = (const float*)d_in[3];
    const float* b1   = (const float*)d_in[4];
    const float* W2   = (const float*)d_in[5];
    const float* b2   = (const float*)d_in[6];
    const float* W3   = (const float*)d_in[7];
    const float* b3   = (const float*)d_in[8];
    const float* Wout = (const float*)d_in[9];
    const float* bout = (const float*)d_in[10];
    const int*   nit  = (const int*)d_in[11];
    float* out = (float*)d_out;

    float *p_Mop, *p_h1, *p_h2, *p_y0;
    cudaGetSymbolAddress((void**)&p_Mop, g_Mop);
    cudaGetSymbolAddress((void**)&p_h1, g_h1);
    cudaGetSymbolAddress((void**)&p_h2, g_h2);
    cudaGetSymbolAddress((void**)&p_y0, g_y0);

    gemm_kernel<<<dim3(H_DIM / 64, B_ROWS / 64), 256>>>(x,    W1,   b1,   p_h1, D_INF, H_DIM, 1);
    gemm_kernel<<<dim3(H_DIM / 64, B_ROWS / 64), 256>>>(p_h1, W2,   b2,   p_h2, H_DIM, H_DIM, 1);
    gemm_kernel<<<dim3(H_DIM / 64, B_ROWS / 64), 256>>>(p_h2, W3,   b3,   p_h1, H_DIM, H_DIM, 1);
    gemm_kernel<<<dim3(D_OUT / 64, B_ROWS / 64), 256>>>(p_h1, Wout, bout, p_y0, H_DIM, D_OUT, 0);

    setup_kernel<<<1, 256>>>(A, p_Mop);

    size_t smem = (size_t)(2 * 64 * 256 + 32 * 68) * sizeof(float);
    cudaFuncSetAttribute(solve_kernel, cudaFuncAttributeMaxDynamicSharedMemorySize, (int)smem);
    solve_kernel<<<B_ROWS / 32, 256, smem>>>(A, bcon, p_y0, p_Mop, nit, out);
}

// round 7
// speedup vs baseline: 1.0649x; 1.0038x over previous
#include <cuda_runtime.h>
#include <cstddef>

#define B_ROWS 4096
#define D_INF  128
#define H_DIM  512
#define D_OUT  256
#define M_CON  64

#define SIGMA_F 1.0f
#define OMEGA_F 1.7f
#define INV_F   0.5f   // 1/(1+SIGMA)

typedef unsigned long long u64;

__device__ __forceinline__ u64 ffma2(u64 a, u64 b, u64 c) {
    u64 d; asm("fma.rn.f32x2 %0,%1,%2,%3;" : "=l"(d) : "l"(a), "l"(b), "l"(c)); return d;
}
__device__ __forceinline__ u64 fadd2(u64 a, u64 b) {
    u64 d; asm("add.rn.f32x2 %0,%1,%2;" : "=l"(d) : "l"(a), "l"(b)); return d;
}
__device__ __forceinline__ u64 fmul2(u64 a, u64 b) {
    u64 d; asm("mul.rn.f32x2 %0,%1,%2;" : "=l"(d) : "l"(a), "l"(b)); return d;
}
__device__ __forceinline__ u64 pack2(float x, float y) {
    u64 d; asm("mov.b64 %0,{%1,%2};" : "=l"(d) : "f"(x), "f"(y)); return d;
}
__device__ __forceinline__ void unpack2(u64 v, float& x, float& y) {
    asm("mov.b64 {%0,%1},%2;" : "=f"(x), "=f"(y) : "l"(v));
}

__device__ float g_Mop[M_CON * D_OUT];
__device__ float g_h1[B_ROWS * H_DIM];
__device__ float g_h2[B_ROWS * H_DIM];
__device__ float g_y0[B_ROWS * D_OUT];

// ---------------------------------------------------------------------------
// Setup: Mop = inv(A A^T) @ A.   A is [64, 256]. Single CTA, 256 threads.
// ---------------------------------------------------------------------------
__global__ void __launch_bounds__(256) setup_kernel(const float* __restrict__ A,
                                                    float* __restrict__ Mop) {
    __shared__ float Gs[64][65];
    __shared__ float Ks[64][65];
    __shared__ float fcol[64];
    int tid = threadIdx.x;

    for (int idx = tid; idx < 64 * 64; idx += 256) {
        int i = idx >> 6, j = idx & 63;
        float s = 0.f;
        const float* ai = A + (size_t)i * D_OUT;
        const float* aj = A + (size_t)j * D_OUT;
        #pragma unroll 8
        for (int d = 0; d < D_OUT; d++) s += ai[d] * aj[d];
        Gs[i][j] = s;
        Ks[i][j] = (i == j) ? 1.f : 0.f;
    }
    __syncthreads();

    for (int k = 0; k < 64; k++) {
        float pinv = 1.f / Gs[k][k];
        if (tid < 64) fcol[tid] = Gs[tid][k];
        __syncthreads();
        if (tid < 64) {
            Gs[k][tid] *= pinv;
            Ks[k][tid] *= pinv;
        }
        __syncthreads();
        for (int idx = tid; idx < 64 * 64; idx += 256) {
            int i = idx >> 6, j = idx & 63;
            if (i != k) {
                float f = fcol[i];
                Gs[i][j] -= f * Gs[k][j];
                Ks[i][j] -= f * Ks[k][j];
            }
        }
        __syncthreads();
    }

    for (int idx = tid; idx < 64 * D_OUT; idx += 256) {
        int m = idx >> 8, d = idx & 255;
        float s = 0.f;
        #pragma unroll 8
        for (int j = 0; j < 64; j++) s += Ks[m][j] * A[(size_t)j * D_OUT + d];
        Mop[(size_t)m * D_OUT + d] = s;
    }
}

// ---------------------------------------------------------------------------
// Trunk GEMM: C[B,N] = act(X[B,K] @ W[K,N] + b).  64x64 tile, 256 threads,
// 4x4 micro-tile, K-step 16, double-buffered smem, global->reg prefetch,
// peeled last iteration (branch-free steady-state body).
// ---------------------------------------------------------------------------
__global__ void __launch_bounds__(256) gemm_kernel(const float* __restrict__ X,
                                                   const float* __restrict__ W,
                                                   const float* __restrict__ bias,
                                                   float* __restrict__ C,
                                                   int K, int N, int do_relu) {
    __shared__ float Xs[2][16][68];   // transposed: Xs[buf][k][m]
    __shared__ float Ws[2][16][64];

    int tid = threadIdx.x;
    int cb = blockIdx.x * 64;
    int rb = blockIdx.y * 64;
    int ty = tid >> 4, tx = tid & 15;

    u64 acc[4][2];
    #pragma unroll
    for (int i = 0; i < 4; i++) { acc[i][0] = 0ull; acc[i][1] = 0ull; }

    int xr = tid >> 2;
    int xc = (tid & 3) * 4;
    int wr = tid >> 4;
    int wc = (tid & 15) * 4;

    const float* Xp = X + (size_t)(rb + xr) * K + xc;
    const float* Wp = W + (size_t)wr * N + cb + wc;

    float4 xv = *(const float4*)(Xp);
    float4 wv = *(const float4*)(Wp);
    Xs[0][xc + 0][xr] = xv.x;
    Xs[0][xc + 1][xr] = xv.y;
    Xs[0][xc + 2][xr] = xv.z;
    Xs[0][xc + 3][xr] = xv.w;
    *(float4*)&Ws[0][wr][wc] = wv;
    __syncthreads();

    int nk = K >> 4;
    for (int ks = 0; ks < nk - 1; ks++) {
        int p = ks & 1;
        xv = *(const float4*)(Xp + (ks + 1) * 16);
        wv = *(const float4*)(Wp + (size_t)(ks + 1) * 16 * N);
        #pragma unroll
        for (int kk = 0; kk < 16; kk++) {
            float4 a4 = *(float4*)&Xs[p][kk][ty * 4];
            ulonglong2 b = *(ulonglong2*)&Ws[p][kk][tx * 4];
            u64 a0 = pack2(a4.x, a4.x);
            u64 a1 = pack2(a4.y, a4.y);
            u64 a2 = pack2(a4.z, a4.z);
            u64 a3 = pack2(a4.w, a4.w);
            acc[0][0] = ffma2(a0, b.x, acc[0][0]); acc[0][1] = ffma2(a0, b.y, acc[0][1]);
            acc[1][0] = ffma2(a1, b.x, acc[1][0]); acc[1][1] = ffma2(a1, b.y, acc[1][1]);
            acc[2][0] = ffma2(a2, b.x, acc[2][0]); acc[2][1] = ffma2(a2, b.y, acc[2][1]);
            acc[3][0] = ffma2(a3, b.x, acc[3][0]); acc[3][1] = ffma2(a3, b.y, acc[3][1]);
        }
        int pn = p ^ 1;
        Xs[pn][xc + 0][xr] = xv.x;
        Xs[pn][xc + 1][xr] = xv.y;
        Xs[pn][xc + 2][xr] = xv.z;
        Xs[pn][xc + 3][xr] = xv.w;
        *(float4*)&Ws[pn][wr][wc] = wv;
        __syncthreads();
    }
    {   // last K-step (no prefetch)
        int p = (nk - 1) & 1;
        #pragma unroll
        for (int kk = 0; kk < 16; kk++) {
            float4 a4 = *(float4*)&Xs[p][kk][ty * 4];
            ulonglong2 b = *(ulonglong2*)&Ws[p][kk][tx * 4];
            u64 a0 = pack2(a4.x, a4.x);
            u64 a1 = pack2(a4.y, a4.y);
            u64 a2 = pack2(a4.z, a4.z);
            u64 a3 = pack2(a4.w, a4.w);
            acc[0][0] = ffma2(a0, b.x, acc[0][0]); acc[0][1] = ffma2(a0, b.y, acc[0][1]);
            acc[1][0] = ffma2(a1, b.x, acc[1][0]); acc[1][1] = ffma2(a1, b.y, acc[1][1]);
            acc[2][0] = ffma2(a2, b.x, acc[2][0]); acc[2][1] = ffma2(a2, b.y, acc[2][1]);
            acc[3][0] = ffma2(a3, b.x, acc[3][0]); acc[3][1] = ffma2(a3, b.y, acc[3][1]);
        }
    }

    float4 bv = *(const float4*)(bias + cb + tx * 4);
    #pragma unroll
    for (int i = 0; i < 4; i++) {
        int row = rb + ty * 4 + i;
        float4 o;
        unpack2(acc[i][0], o.x, o.y);
        unpack2(acc[i][1], o.z, o.w);
        o.x += bv.x; o.y += bv.y; o.z += bv.z; o.w += bv.w;
        if (do_relu) {
            o.x = fmaxf(o.x, 0.f); o.y = fmaxf(o.y, 0.f);
            o.z = fmaxf(o.z, 0.f); o.w = fmaxf(o.w, 0.f);
        }
        *(float4*)(C + (size_t)row * N + cb + tx * 4) = o;
    }
}

// ---------------------------------------------------------------------------
// Solver: persistent per-row-block Douglas-Rachford, f32x2 math.
// CTA = 256 threads = 8 warps; 32 rows per CTA.
// warp w: rows w*4 + (lane&3); lane>>2 = d-chunk (8 chunks x 32 floats).
// A, Mop, y0-block, c-block in dynamic shared. z/v/y state in registers.
// m-groups processed in software-pipelined PAIRS so the two shuffle-reduce
// chains interleave and hide each other's latency.
// ---------------------------------------------------------------------------
__global__ void __launch_bounds__(256, 1) solve_kernel(
    const float* __restrict__ A, const float* __restrict__ bcon,
    const float* __restrict__ y0g, const float* __restrict__ Mop,
    const int* __restrict__ p_niter, float* __restrict__ out) {
    extern __shared__ float sm[];
    float* As  = sm;                    // 64*256
    float* Ms  = As + 64 * 256;         // 64*256
    float* Y0s = Ms + 64 * 256;         // 32*256
    float* Cs  = Y0s + 32 * 256;        // 32*256
    float* Bs  = Cs + 32 * 256;         // 32*68

    int tid = threadIdx.x;
    int rb = blockIdx.x * 32;

    {
        const float4* A4 = (const float4*)A;
        const float4* M4 = (const float4*)Mop;
        float4* As4s = (float4*)As;
        float4* Ms4s = (float4*)Ms;
        #pragma unroll
        for (int i = 0; i < 16; i++) {
            As4s[tid + i * 256] = A4[tid + i * 256];
            Ms4s[tid + i * 256] = M4[tid + i * 256];
        }
        // y0 block straight copy [32][256]
        const float4* y4 = (const float4*)(y0g + (size_t)rb * D_OUT);
        float4* Y0s4 = (float4*)Y0s;
        #pragma unroll
        for (int i = 0; i < 8; i++) Y0s4[tid + i * 256] = y4[tid + i * 256];
        // bcon block 32x64 -> padded 32x68
        const float4* bc4 = (const float4*)(bcon + (size_t)rb * M_CON);
        #pragma unroll
        for (int i = 0; i < 2; i++) {
            int fl = tid + i * 256;
            float4 v = bc4[fl];
            int r = fl >> 4;
            int c = (fl & 15) * 4;
            Bs[r * 68 + c + 0] = v.x;
            Bs[r * 68 + c + 1] = v.y;
            Bs[r * 68 + c + 2] = v.z;
            Bs[r * 68 + c + 3] = v.w;
        }
    }
    __syncthreads();

    int lane  = tid & 31;
    int w     = tid >> 5;
    int r4    = lane & 3;
    int chunk = lane >> 2;
    int row_l = w * 4 + r4;
    int row_g = rb + row_l;
    int cb4   = chunk * 8;

    int idxq[8];
    #pragma unroll
    for (int q = 0; q < 8; q++) idxq[q] = cb4 + ((q + chunk) & 7);  // conflict-free rotation

    const ulonglong2* As2  = (const ulonglong2*)As;   // 16B units
    const ulonglong2* Ms2  = (const ulonglong2*)Ms;
    const ulonglong2* Y0s2 = (const ulonglong2*)Y0s;
    ulonglong2*       Cs2  = (ulonglong2*)Cs;

    u64 zr[16], vr[16], yv[16];

    // init z = y0 (read own slots from smem copy)
    #pragma unroll
    for (int q = 0; q < 8; q++) {
        ulonglong2 t = Y0s2[row_l * 64 + idxq[q]];
        zr[2 * q] = t.x; zr[2 * q + 1] = t.y;
    }

    // c = bcon @ Mop, then park in smem (read back each iteration)
    {
        u64 cr[16];
        #pragma unroll
        for (int j = 0; j < 16; j++) cr[j] = 0ull;
        #pragma unroll 8
        for (int m = 0; m < 64; m++) {
            float bm = Bs[row_l * 68 + m];
            u64 bm2 = pack2(bm, bm);
            #pragma unroll
            for (int q = 0; q < 8; q++) {
                ulonglong2 ms = Ms2[m * 64 + idxq[q]];
                cr[2 * q]     = ffma2(bm2, ms.x, cr[2 * q]);
                cr[2 * q + 1] = ffma2(bm2, ms.y, cr[2 * q + 1]);
            }
        }
        #pragma unroll
        for (int q = 0; q < 8; q++) {
            ulonglong2 t; t.x = cr[2 * q]; t.y = cr[2 * q + 1];
            Cs2[row_l * 64 + idxq[q]] = t;
        }
    }

    const u64 half2 = pack2(INV_F, INV_F);
    int niter = *p_niter;

    #pragma unroll 1
    for (int it = 0; it < niter; it++) {
        // v = (z + y0)/2 ; y = v + c
        #pragma unroll
        for (int q = 0; q < 8; q++) {
            ulonglong2 y0q = Y0s2[row_l * 64 + idxq[q]];
            ulonglong2 cq  = Cs2[row_l * 64 + idxq[q]];
            vr[2 * q]     = fmul2(fadd2(zr[2 * q],     y0q.x), half2);
            vr[2 * q + 1] = fmul2(fadd2(zr[2 * q + 1], y0q.y), half2);
            yv[2 * q]     = fadd2(vr[2 * q],     cq.x);
            yv[2 * q + 1] = fadd2(vr[2 * q + 1], cq.y);
        }

        // y -= (v A^T) Mop : m-groups of 8, software-pipelined in PAIRS
        for (int gp = 0; gp < 4; gp++) {
            int mo0 = gp * 16;
            int mo1 = mo0 + 8;
            float rgA[8], rgB[8];

            // G1 partials for both groups (independent work back-to-back)
            #pragma unroll
            for (int mi = 0; mi < 8; mi++) {
                u64 a0 = 0ull, a1 = 0ull, a2 = 0ull, a3 = 0ull;
                #pragma unroll
                for (int q = 0; q < 8; q += 4) {
                    ulonglong2 t0 = As2[(mo0 + mi) * 64 + idxq[q]];
                    ulonglong2 t1 = As2[(mo0 + mi) * 64 + idxq[q + 1]];
                    ulonglong2 t2 = As2[(mo0 + mi) * 64 + idxq[q + 2]];
                    ulonglong2 t3 = As2[(mo0 + mi) * 64 + idxq[q + 3]];
                    a0 = ffma2(vr[2 * q],     t0.x, a0); a0 = ffma2(vr[2 * q + 1], t0.y, a0);
                    a1 = ffma2(vr[2 * q + 2], t1.x, a1); a1 = ffma2(vr[2 * q + 3], t1.y, a1);
                    a2 = ffma2(vr[2 * q + 4], t2.x, a2); a2 = ffma2(vr[2 * q + 5], t2.y, a2);
                    a3 = ffma2(vr[2 * q + 6], t3.x, a3); a3 = ffma2(vr[2 * q + 7], t3.y, a3);
                }
                u64 s = fadd2(fadd2(a0, a1), fadd2(a2, a3));
                float lo, hi; unpack2(s, lo, hi);
                rgA[mi] = lo + hi;
            }
            #pragma unroll
            for (int mi = 0; mi < 8; mi++) {
                u64 a0 = 0ull, a1 = 0ull, a2 = 0ull, a3 = 0ull;
                #pragma unroll
                for (int q = 0; q < 8; q += 4) {
                    ulonglong2 t0 = As2[(mo1 + mi) * 64 + idxq[q]];
                    ulonglong2 t1 = As2[(mo1 + mi) * 64 + idxq[q + 1]];
                    ulonglong2 t2 = As2[(mo1 + mi) * 64 + idxq[q + 2]];
                    ulonglong2 t3 = As2[(mo1 + mi) * 64 + idxq[q + 3]];
                    a0 = ffma2(vr[2 * q],     t0.x, a0); a0 = ffma2(vr[2 * q + 1], t0.y, a0);
                    a1 = ffma2(vr[2 * q + 2], t1.x, a1); a1 = ffma2(vr[2 * q + 3], t1.y, a1);
                    a2 = ffma2(vr[2 * q + 4], t2.x, a2); a2 = ffma2(vr[2 * q + 5], t2.y, a2);
                    a3 = ffma2(vr[2 * q + 6], t3.x, a3); a3 = ffma2(vr[2 * q + 7], t3.y, a3);
                }
                u64 s = fadd2(fadd2(a0, a1), fadd2(a2, a3));
                float lo, hi; unpack2(s, lo, hi);
                rgB[mi] = lo + hi;
            }

            // two independent shuffle-reduce trees, interleaved
            #pragma unroll
            for (int l = 4; l <= 16; l <<= 1) {
                #pragma unroll
                for (int mi = 0; mi < 8; mi++)
                    rgA[mi] += __shfl_xor_sync(0xffffffffu, rgA[mi], l);
                #pragma unroll
                for (int mi = 0; mi < 8; mi++)
                    rgB[mi] += __shfl_xor_sync(0xffffffffu, rgB[mi], l);
            }

            // G2 for both groups
            #pragma unroll
            for (int mi = 0; mi < 8; mi++) {
                float nrm = -rgA[mi];
                u64 nrm2 = pack2(nrm, nrm);
                #pragma unroll
                for (int q = 0; q < 8; q++) {
                    ulonglong2 ms = Ms2[(mo0 + mi) * 64 + idxq[q]];
                    yv[2 * q]     = ffma2(nrm2, ms.x, yv[2 * q]);
                    yv[2 * q + 1] = ffma2(nrm2, ms.y, yv[2 * q + 1]);
                }
            }
            #pragma unroll
            for (int mi = 0; mi < 8; mi++) {
                float nrm = -rgB[mi];
                u64 nrm2 = pack2(nrm, nrm);
                #pragma unroll
                for (int q = 0; q < 8; q++) {
                    ulonglong2 ms = Ms2[(mo1 + mi) * 64 + idxq[q]];
                    yv[2 * q]     = ffma2(nrm2, ms.x, yv[2 * q]);
                    yv[2 * q + 1] = ffma2(nrm2, ms.y, yv[2 * q + 1]);
                }
            }
        }

        // z += omega * (max(2y - z, 0) - y)
        #pragma unroll
        for (int j = 0; j < 16; j++) {
            float y0f, y1f, z0f, z1f;
            unpack2(yv[j], y0f, y1f);
            unpack2(zr[j], z0f, z1f);
            float w0 = fmaxf(2.f * y0f - z0f, 0.f);
            float w1 = fmaxf(2.f * y1f - z1f, 0.f);
            z0f += OMEGA_F * (w0 - y0f);
            z1f += OMEGA_F * (w1 - y1f);
            zr[j] = pack2(z0f, z1f);
        }
    }

    ulonglong2* orow = (ulonglong2*)(out + (size_t)row_g * D_OUT);
    #pragma unroll
    for (int q = 0; q < 8; q++) {
        ulonglong2 t;
        t.x = yv[2 * q];
        t.y = yv[2 * q + 1];
        orow[idxq[q]] = t;
    }
}

// ---------------------------------------------------------------------------
extern "C" void kernel_launch(void* const* d_in, const int* in_sizes, int n_in,
                              void* d_out, int out_size) {
    const float* x    = (const float*)d_in[0];
    const float* bcon = (const float*)d_in[1];
    const float* A    = (const float*)d_in[2];
    const float* W1   = (const float*)d_in[3];
    const float* b1   = (const float*)d_in[4];
    const float* W2   = (const float*)d_in[5];
    const float* b2   = (const float*)d_in[6];
    const float* W3   = (const float*)d_in[7];
    const float* b3   = (const float*)d_in[8];
    const float* Wout = (const float*)d_in[9];
    const float* bout = (const float*)d_in[10];
    const int*   nit  = (const int*)d_in[11];
    float* out = (float*)d_out;

    float *p_Mop, *p_h1, *p_h2, *p_y0;
    cudaGetSymbolAddress((void**)&p_Mop, g_Mop);
    cudaGetSymbolAddress((void**)&p_h1, g_h1);
    cudaGetSymbolAddress((void**)&p_h2, g_h2);
    cudaGetSymbolAddress((void**)&p_y0, g_y0);

    gemm_kernel<<<dim3(H_DIM / 64, B_ROWS / 64), 256>>>(x,    W1,   b1,   p_h1, D_INF, H_DIM, 1);
    gemm_kernel<<<dim3(H_DIM / 64, B_ROWS / 64), 256>>>(p_h1, W2,   b2,   p_h2, H_DIM, H_DIM, 1);
    gemm_kernel<<<dim3(H_DIM / 64, B_ROWS / 64), 256>>>(p_h2, W3,   b3,   p_h1, H_DIM, H_DIM, 1);
    gemm_kernel<<<dim3(D_OUT / 64, B_ROWS / 64), 256>>>(p_h1, Wout, bout, p_y0, H_DIM, D_OUT, 0);

    setup_kernel<<<1, 256>>>(A, p_Mop);

    size_t smem = (size_t)(2 * 64 * 256 + 2 * 32 * 256 + 32 * 68) * sizeof(float);
    cudaFuncSetAttribute(solve_kernel, cudaFuncAttributeMaxDynamicSharedMemorySize, (int)smem);
    solve_kernel<<<B_ROWS / 32, 256, smem>>>(A, bcon, p_y0, p_Mop, nit, out);
}

// round 8
// speedup vs baseline: 1.1829x; 1.1108x over previous
#include <cuda_runtime.h>
#include <cstddef>

#define B_ROWS 4096
#define D_INF  128
#define H_DIM  512
#define D_OUT  256
#define M_CON  64

#define OMEGA_F 1.7f

typedef unsigned long long u64;

__device__ __forceinline__ u64 ffma2(u64 a, u64 b, u64 c) {
    u64 d; asm("fma.rn.f32x2 %0,%1,%2,%3;" : "=l"(d) : "l"(a), "l"(b), "l"(c)); return d;
}
__device__ __forceinline__ u64 fadd2(u64 a, u64 b) {
    u64 d; asm("add.rn.f32x2 %0,%1,%2;" : "=l"(d) : "l"(a), "l"(b)); return d;
}
__device__ __forceinline__ u64 fmul2(u64 a, u64 b) {
    u64 d; asm("mul.rn.f32x2 %0,%1,%2;" : "=l"(d) : "l"(a), "l"(b)); return d;
}
__device__ __forceinline__ u64 pack2(float x, float y) {
    u64 d; asm("mov.b64 %0,{%1,%2};" : "=l"(d) : "f"(x), "f"(y)); return d;
}
__device__ __forceinline__ void unpack2(u64 v, float& x, float& y) {
    asm("mov.b64 {%0,%1},%2;" : "=f"(x), "=f"(y) : "l"(v));
}

__device__ float g_Mop[M_CON * D_OUT];
__device__ float g_h1[B_ROWS * H_DIM];
__device__ float g_h2[B_ROWS * H_DIM];
__device__ float g_y0[B_ROWS * D_OUT];

// ---------------------------------------------------------------------------
// Setup: Mop = inv(A A^T) @ A.   A is [64, 256]. Single CTA, 256 threads.
// ---------------------------------------------------------------------------
__global__ void __launch_bounds__(256) setup_kernel(const float* __restrict__ A,
                                                    float* __restrict__ Mop) {
    __shared__ float Gs[64][65];
    __shared__ float Ks[64][65];
    __shared__ float fcol[64];
    int tid = threadIdx.x;

    for (int idx = tid; idx < 64 * 64; idx += 256) {
        int i = idx >> 6, j = idx & 63;
        float s = 0.f;
        const float* ai = A + (size_t)i * D_OUT;
        const float* aj = A + (size_t)j * D_OUT;
        #pragma unroll 8
        for (int d = 0; d < D_OUT; d++) s += ai[d] * aj[d];
        Gs[i][j] = s;
        Ks[i][j] = (i == j) ? 1.f : 0.f;
    }
    __syncthreads();

    for (int k = 0; k < 64; k++) {
        float pinv = 1.f / Gs[k][k];
        if (tid < 64) fcol[tid] = Gs[tid][k];
        __syncthreads();
        if (tid < 64) {
            Gs[k][tid] *= pinv;
            Ks[k][tid] *= pinv;
        }
        __syncthreads();
        for (int idx = tid; idx < 64 * 64; idx += 256) {
            int i = idx >> 6, j = idx & 63;
            if (i != k) {
                float f = fcol[i];
                Gs[i][j] -= f * Gs[k][j];
                Ks[i][j] -= f * Ks[k][j];
            }
        }
        __syncthreads();
    }

    for (int idx = tid; idx < 64 * D_OUT; idx += 256) {
        int m = idx >> 8, d = idx & 255;
        float s = 0.f;
        #pragma unroll 8
        for (int j = 0; j < 64; j++) s += Ks[m][j] * A[(size_t)j * D_OUT + d];
        Mop[(size_t)m * D_OUT + d] = s;
    }
}

// ---------------------------------------------------------------------------
// Trunk GEMM (unchanged from best passing version): 64x64 tile, 256 threads,
// double-buffered smem, register prefetch, peeled last K-step.
// ---------------------------------------------------------------------------
__global__ void __launch_bounds__(256) gemm_kernel(const float* __restrict__ X,
                                                   const float* __restrict__ W,
                                                   const float* __restrict__ bias,
                                                   float* __restrict__ C,
                                                   int K, int N, int do_relu) {
    __shared__ float Xs[2][16][68];
    __shared__ float Ws[2][16][64];

    int tid = threadIdx.x;
    int cb = blockIdx.x * 64;
    int rb = blockIdx.y * 64;
    int ty = tid >> 4, tx = tid & 15;

    u64 acc[4][2];
    #pragma unroll
    for (int i = 0; i < 4; i++) { acc[i][0] = 0ull; acc[i][1] = 0ull; }

    int xr = tid >> 2;
    int xc = (tid & 3) * 4;
    int wr = tid >> 4;
    int wc = (tid & 15) * 4;

    const float* Xp = X + (size_t)(rb + xr) * K + xc;
    const float* Wp = W + (size_t)wr * N + cb + wc;

    float4 xv = *(const float4*)(Xp);
    float4 wv = *(const float4*)(Wp);
    Xs[0][xc + 0][xr] = xv.x;
    Xs[0][xc + 1][xr] = xv.y;
    Xs[0][xc + 2][xr] = xv.z;
    Xs[0][xc + 3][xr] = xv.w;
    *(float4*)&Ws[0][wr][wc] = wv;
    __syncthreads();

    int nk = K >> 4;
    for (int ks = 0; ks < nk - 1; ks++) {
        int p = ks & 1;
        xv = *(const float4*)(Xp + (ks + 1) * 16);
        wv = *(const float4*)(Wp + (size_t)(ks + 1) * 16 * N);
        #pragma unroll
        for (int kk = 0; kk < 16; kk++) {
            float4 a4 = *(float4*)&Xs[p][kk][ty * 4];
            ulonglong2 b = *(ulonglong2*)&Ws[p][kk][tx * 4];
            u64 a0 = pack2(a4.x, a4.x);
            u64 a1 = pack2(a4.y, a4.y);
            u64 a2 = pack2(a4.z, a4.z);
            u64 a3 = pack2(a4.w, a4.w);
            acc[0][0] = ffma2(a0, b.x, acc[0][0]); acc[0][1] = ffma2(a0, b.y, acc[0][1]);
            acc[1][0] = ffma2(a1, b.x, acc[1][0]); acc[1][1] = ffma2(a1, b.y, acc[1][1]);
            acc[2][0] = ffma2(a2, b.x, acc[2][0]); acc[2][1] = ffma2(a2, b.y, acc[2][1]);
            acc[3][0] = ffma2(a3, b.x, acc[3][0]); acc[3][1] = ffma2(a3, b.y, acc[3][1]);
        }
        int pn = p ^ 1;
        Xs[pn][xc + 0][xr] = xv.x;
        Xs[pn][xc + 1][xr] = xv.y;
        Xs[pn][xc + 2][xr] = xv.z;
        Xs[pn][xc + 3][xr] = xv.w;
        *(float4*)&Ws[pn][wr][wc] = wv;
        __syncthreads();
    }
    {
        int p = (nk - 1) & 1;
        #pragma unroll
        for (int kk = 0; kk < 16; kk++) {
            float4 a4 = *(float4*)&Xs[p][kk][ty * 4];
            ulonglong2 b = *(ulonglong2*)&Ws[p][kk][tx * 4];
            u64 a0 = pack2(a4.x, a4.x);
            u64 a1 = pack2(a4.y, a4.y);
            u64 a2 = pack2(a4.z, a4.z);
            u64 a3 = pack2(a4.w, a4.w);
            acc[0][0] = ffma2(a0, b.x, acc[0][0]); acc[0][1] = ffma2(a0, b.y, acc[0][1]);
            acc[1][0] = ffma2(a1, b.x, acc[1][0]); acc[1][1] = ffma2(a1, b.y, acc[1][1]);
            acc[2][0] = ffma2(a2, b.x, acc[2][0]); acc[2][1] = ffma2(a2, b.y, acc[2][1]);
            acc[3][0] = ffma2(a3, b.x, acc[3][0]); acc[3][1] = ffma2(a3, b.y, acc[3][1]);
        }
    }

    float4 bv = *(const float4*)(bias + cb + tx * 4);
    #pragma unroll
    for (int i = 0; i < 4; i++) {
        int row = rb + ty * 4 + i;
        float4 o;
        unpack2(acc[i][0], o.x, o.y);
        unpack2(acc[i][1], o.z, o.w);
        o.x += bv.x; o.y += bv.y; o.z += bv.z; o.w += bv.w;
        if (do_relu) {
            o.x = fmaxf(o.x, 0.f); o.y = fmaxf(o.y, 0.f);
            o.z = fmaxf(o.z, 0.f); o.w = fmaxf(o.w, 0.f);
        }
        *(float4*)(C + (size_t)row * N + cb + tx * 4) = o;
    }
}

// ---------------------------------------------------------------------------
// Solver v3: lane-distinct smem reads + transpose-reduce.
// CTA = 256 threads = 8 warps; warp owns 4 rows; lane owns d-slice
// {l*4..l*4+3, 128+l*4..l*4+131} for all 4 rows (state in registers).
// Iteration (z-only form):
//   g[m]  = z . A[m]                      (G1, lane-partial + transpose-reduce)
//   rm    = -(0.5*g[m] + rho0[row][m])    (rho0 = 0.5*y0 A^T, precomputed)
//   p     = sum_m rm * Mop[m]             (G2; p holds NEGATIVE correction)
//   u     = t0 + p                        (t0 = 0.5*y0 + bcon*Mop, precomputed)
//   y     = 0.5*z + u    (output on last iter)
//   z    <- 0.15*z + 1.7*|u|              (z' = (1-w/2) z + w |u|)
// ---------------------------------------------------------------------------

// transpose-reduce over P[32]: after this, lane j holds sum over all lanes of
// P[j] (value idx j ends at lane j). 31 shfl total.
#define TREDUCE_LEVEL(d, n)                                               \
    _Pragma("unroll")                                                     \
    for (int i = 0; i < (n); i++) {                                       \
        float send = (lane & (d)) ? P[i] : P[i + (n)];                    \
        float recv = __shfl_xor_sync(0xffffffffu, send, (d));             \
        float keep = (lane & (d)) ? P[i + (n)] : P[i];                    \
        P[i] = keep + recv;                                               \
    }

__global__ void __launch_bounds__(256, 1) solve_kernel(
    const float* __restrict__ A, const float* __restrict__ bcon,
    const float* __restrict__ y0g, const float* __restrict__ Mop,
    const int* __restrict__ p_niter, float* __restrict__ out) {
    extern __shared__ float sm[];
    float* As  = sm;                    // 64*256 = 16384 floats
    float* Ms  = As + 64 * 256;         // 16384
    float* T0  = Ms + 64 * 256;         // 32*256 = 8192
    float* Rho = T0 + 32 * 256;         // 32*72  = 2304  (also Bs in prologue)

    int tid = threadIdx.x;
    int rb = blockIdx.x * 32;

    // ---- cooperative loads ----
    {
        const float4* A4 = (const float4*)A;
        const float4* M4 = (const float4*)Mop;
        float4* As4 = (float4*)As;
        float4* Ms4 = (float4*)Ms;
        #pragma unroll
        for (int i = 0; i < 16; i++) {
            As4[tid + i * 256] = A4[tid + i * 256];
            Ms4[tid + i * 256] = M4[tid + i * 256];
        }
        // bcon block [32][64] -> Rho region as Bs with stride 72
        const float4* bc4 = (const float4*)(bcon + (size_t)rb * M_CON);
        #pragma unroll
        for (int i = 0; i < 2; i++) {
            int idx4 = tid + i * 256;          // 0..511 float4s
            float4 v = bc4[idx4];
            int row = idx4 >> 4;
            int c4  = (idx4 & 15) * 4;
            Rho[row * 72 + c4 + 0] = v.x;
            Rho[row * 72 + c4 + 1] = v.y;
            Rho[row * 72 + c4 + 2] = v.z;
            Rho[row * 72 + c4 + 3] = v.w;
        }
    }
    __syncthreads();

    int lane = tid & 31;
    int w    = tid >> 5;
    int wrb  = w * 4;                    // local row base (0..28)

    const ulonglong2* As2 = (const ulonglong2*)As;   // float4 units
    const ulonglong2* Ms2 = (const ulonglong2*)Ms;

    // ---- z init = y0 (registers), 4 rows x 4 u64 (8 floats: lo4 @ l*4, hi4 @ 128+l*4)
    u64 z[4][4];
    #pragma unroll
    for (int r = 0; r < 4; r++) {
        const ulonglong2* yp = (const ulonglong2*)(y0g + (size_t)(rb + wrb + r) * D_OUT);
        ulonglong2 lo = yp[lane];
        ulonglong2 hi = yp[32 + lane];
        z[r][0] = lo.x; z[r][1] = lo.y; z[r][2] = hi.x; z[r][3] = hi.y;
    }

    // ---- c = bcon @ Mop (registers), then t0 = 0.5*y0 + c -> smem T0
    {
        u64 c[4][4];
        #pragma unroll
        for (int r = 0; r < 4; r++)
            #pragma unroll
            for (int j = 0; j < 4; j++) c[r][j] = 0ull;
        #pragma unroll 4
        for (int m = 0; m < 64; m++) {
            ulonglong2 mlo = Ms2[m * 64 + lane];
            ulonglong2 mhi = Ms2[m * 64 + 32 + lane];
            #pragma unroll
            for (int r = 0; r < 4; r++) {
                float bv = Rho[(wrb + r) * 72 + m];   // warp-uniform broadcast
                u64 b2 = pack2(bv, bv);
                c[r][0] = ffma2(b2, mlo.x, c[r][0]);
                c[r][1] = ffma2(b2, mlo.y, c[r][1]);
                c[r][2] = ffma2(b2, mhi.x, c[r][2]);
                c[r][3] = ffma2(b2, mhi.y, c[r][3]);
            }
        }
        const u64 half2 = pack2(0.5f, 0.5f);
        #pragma unroll
        for (int r = 0; r < 4; r++) {
            ulonglong2* tp = (ulonglong2*)(T0 + (size_t)(wrb + r) * D_OUT);
            ulonglong2 lo, hi;
            lo.x = ffma2(half2, z[r][0], c[r][0]);
            lo.y = ffma2(half2, z[r][1], c[r][1]);
            hi.x = ffma2(half2, z[r][2], c[r][2]);
            hi.y = ffma2(half2, z[r][3], c[r][3]);
            tp[lane] = lo;
            tp[32 + lane] = hi;
        }
    }
    __syncthreads();   // all warps done reading Bs; T0 visible

    int jr = lane >> 3, jk = lane & 7;   // this lane's (row, k) after reduce

    // ---- rho0 = 0.5 * (y0 A^T): one G1 pass on z(=y0), store to Rho (overwrites Bs)
    #pragma unroll 1
    for (int g = 0; g < 8; g++) {
        int mo = g * 8;
        float P[32];
        #pragma unroll
        for (int k = 0; k < 8; k++) {
            int m = mo + k;
            ulonglong2 alo = As2[m * 64 + lane];
            ulonglong2 ahi = As2[m * 64 + 32 + lane];
            #pragma unroll
            for (int r = 0; r < 4; r++) {
                u64 acc = fmul2(z[r][0], alo.x);
                acc = ffma2(z[r][1], alo.y, acc);
                acc = ffma2(z[r][2], ahi.x, acc);
                acc = ffma2(z[r][3], ahi.y, acc);
                float lo, hi; unpack2(acc, lo, hi);
                P[r * 8 + k] = lo + hi;
            }
        }
        TREDUCE_LEVEL(16, 16)
        TREDUCE_LEVEL(8, 8)
        TREDUCE_LEVEL(4, 4)
        TREDUCE_LEVEL(2, 2)
        TREDUCE_LEVEL(1, 1)
        Rho[(wrb + jr) * 72 + mo + jk] = 0.5f * P[0];
    }
    __syncthreads();

    int niter = *p_niter;
    if (niter <= 0) {
        // y = y0
        #pragma unroll
        for (int r = 0; r < 4; r++) {
            ulonglong2* op = (ulonglong2*)(out + (size_t)(rb + wrb + r) * D_OUT);
            ulonglong2 lo, hi;
            lo.x = z[r][0]; lo.y = z[r][1]; hi.x = z[r][2]; hi.y = z[r][3];
            op[lane] = lo; op[32 + lane] = hi;
        }
        return;
    }

    const u64 half2 = pack2(0.5f, 0.5f);
    const u64 c015  = pack2(1.0f - OMEGA_F * 0.5f, 1.0f - OMEGA_F * 0.5f);
    const u64 c17   = pack2(OMEGA_F, OMEGA_F);
    const u64 amask = 0x7fffffff7fffffffull;

    #pragma unroll 1
    for (int it = 0; it < niter; it++) {
        u64 p[4][4];
        #pragma unroll
        for (int r = 0; r < 4; r++)
            #pragma unroll
            for (int j = 0; j < 4; j++) p[r][j] = 0ull;

        #pragma unroll 1
        for (int g = 0; g < 8; g++) {
            int mo = g * 8;
            float P[32];
            // G1: lane-partial dots of z against A rows mo..mo+7
            #pragma unroll
            for (int k = 0; k < 8; k++) {
                int m = mo + k;
                ulonglong2 alo = As2[m * 64 + lane];
                ulonglong2 ahi = As2[m * 64 + 32 + lane];
                #pragma unroll
                for (int r = 0; r < 4; r++) {
                    u64 acc = fmul2(z[r][0], alo.x);
                    acc = ffma2(z[r][1], alo.y, acc);
                    acc = ffma2(z[r][2], ahi.x, acc);
                    acc = ffma2(z[r][3], ahi.y, acc);
                    float lo, hi; unpack2(acc, lo, hi);
                    P[r * 8 + k] = lo + hi;
                }
            }
            // transpose-reduce: lane j <- sum of P[j] over lanes
            TREDUCE_LEVEL(16, 16)
            TREDUCE_LEVEL(8, 8)
            TREDUCE_LEVEL(4, 4)
            TREDUCE_LEVEL(2, 2)
            TREDUCE_LEVEL(1, 1)
            // rm = -(0.5*g + rho0)  (negated so G2 accumulates -correction)
            float S = fmaf(-0.5f, P[0], -Rho[(wrb + jr) * 72 + mo + jk]);
            // broadcast all 32 rm values
            float bc[32];
            #pragma unroll
            for (int j = 0; j < 32; j++) bc[j] = __shfl_sync(0xffffffffu, S, j);
            // G2: p[r] += rm * Mop[m][slice]
            #pragma unroll
            for (int k = 0; k < 8; k++) {
                int m = mo + k;
                ulonglong2 mlo = Ms2[m * 64 + lane];
                ulonglong2 mhi = Ms2[m * 64 + 32 + lane];
                #pragma unroll
                for (int r = 0; r < 4; r++) {
                    float rv = bc[r * 8 + k];
                    u64 r2 = pack2(rv, rv);
                    p[r][0] = ffma2(r2, mlo.x, p[r][0]);
                    p[r][1] = ffma2(r2, mlo.y, p[r][1]);
                    p[r][2] = ffma2(r2, mhi.x, p[r][2]);
                    p[r][3] = ffma2(r2, mhi.y, p[r][3]);
                }
            }
        }

        // pointwise: u = t0 + p ; y=0.5z+u (last iter) ; z' = 0.15 z + 1.7 |u|
        bool last = (it == niter - 1);
        #pragma unroll
        for (int r = 0; r < 4; r++) {
            const ulonglong2* tp = (const ulonglong2*)(T0 + (size_t)(wrb + r) * D_OUT);
            ulonglong2 tlo = tp[lane];
            ulonglong2 thi = tp[32 + lane];
            u64 u0 = fadd2(tlo.x, p[r][0]);
            u64 u1 = fadd2(tlo.y, p[r][1]);
            u64 u2 = fadd2(thi.x, p[r][2]);
            u64 u3 = fadd2(thi.y, p[r][3]);
            if (last) {
                ulonglong2* op = (ulonglong2*)(out + (size_t)(rb + wrb + r) * D_OUT);
                ulonglong2 lo, hi;
                lo.x = ffma2(half2, z[r][0], u0);
                lo.y = ffma2(half2, z[r][1], u1);
                hi.x = ffma2(half2, z[r][2], u2);
                hi.y = ffma2(half2, z[r][3], u3);
                op[lane] = lo; op[32 + lane] = hi;
            } else {
                z[r][0] = ffma2(c17, u0 & amask, fmul2(c015, z[r][0]));
                z[r][1] = ffma2(c17, u1 & amask, fmul2(c015, z[r][1]));
                z[r][2] = ffma2(c17, u2 & amask, fmul2(c015, z[r][2]));
                z[r][3] = ffma2(c17, u3 & amask, fmul2(c015, z[r][3]));
            }
        }
    }
}

// ---------------------------------------------------------------------------
extern "C" void kernel_launch(void* const* d_in, const int* in_sizes, int n_in,
                              void* d_out, int out_size) {
    const float* x    = (const float*)d_in[0];
    const float* bcon = (const float*)d_in[1];
    const float* A    = (const float*)d_in[2];
    const float* W1   = (const float*)d_in[3];
    const float* b1   = (const float*)d_in[4];
    const float* W2   = (const float*)d_in[5];
    const float* b2   = (const float*)d_in[6];
    const float* W3   = (const float*)d_in[7];
    const float* b3   = (const float*)d_in[8];
    const float* Wout = (const float*)d_in[9];
    const float* bout = (const float*)d_in[10];
    const int*   nit  = (const int*)d_in[11];
    float* out = (float*)d_out;

    float *p_Mop, *p_h1, *p_h2, *p_y0;
    cudaGetSymbolAddress((void**)&p_Mop, g_Mop);
    cudaGetSymbolAddress((void**)&p_h1, g_h1);
    cudaGetSymbolAddress((void**)&p_h2, g_h2);
    cudaGetSymbolAddress((void**)&p_y0, g_y0);

    gemm_kernel<<<dim3(H_DIM / 64, B_ROWS / 64), 256>>>(x,    W1,   b1,   p_h1, D_INF, H_DIM, 1);
    gemm_kernel<<<dim3(H_DIM / 64, B_ROWS / 64), 256>>>(p_h1, W2,   b2,   p_h2, H_DIM, H_DIM, 1);
    gemm_kernel<<<dim3(H_DIM / 64, B_ROWS / 64), 256>>>(p_h2, W3,   b3,   p_h1, H_DIM, H_DIM, 1);
    gemm_kernel<<<dim3(D_OUT / 64, B_ROWS / 64), 256>>>(p_h1, Wout, bout, p_y0, H_DIM, D_OUT, 0);

    setup_kernel<<<1, 256>>>(A, p_Mop);

    size_t smem = (size_t)(2 * 64 * 256 + 32 * 256 + 32 * 72) * sizeof(float);
    cudaFuncSetAttribute(solve_kernel, cudaFuncAttributeMaxDynamicSharedMemorySize, (int)smem);
    solve_kernel<<<B_ROWS / 32, 256, smem>>>(A, bcon, p_y0, p_Mop, nit, out);
}

// round 10
// speedup vs baseline: 1.6822x; 1.4221x over previous
#include <cuda_runtime.h>
#include <cuda_bf16.h>
#include <cstddef>

#define B_ROWS 4096
#define D_INF  128
#define H_DIM  512
#define D_OUT  256
#define M_CON  64

#define OMEGA_F 1.7f

typedef unsigned long long u64;
typedef unsigned int u32;

// ---------------- f32x2 helpers (trunk GEMM) ----------------
__device__ __forceinline__ u64 ffma2(u64 a, u64 b, u64 c) {
    u64 d; asm("fma.rn.f32x2 %0,%1,%2,%3;" : "=l"(d) : "l"(a), "l"(b), "l"(c)); return d;
}
__device__ __forceinline__ u64 pack2(float x, float y) {
    u64 d; asm("mov.b64 %0,{%1,%2};" : "=l"(d) : "f"(x), "f"(y)); return d;
}
__device__ __forceinline__ void unpack2(u64 v, float& x, float& y) {
    asm("mov.b64 {%0,%1},%2;" : "=f"(x), "=f"(y) : "l"(v));
}

// ---------------- bf16 split helpers ----------------
// pack_bf16(lo,hi): low 16 bits = bf16(lo), high 16 = bf16(hi)
__device__ __forceinline__ u32 pack_bf16(float lo, float hi) {
    u32 d; asm("cvt.rn.bf16x2.f32 %0, %1, %2;" : "=r"(d) : "f"(hi), "f"(lo)); return d;
}
__device__ __forceinline__ float bflo(u32 p) { return __uint_as_float(p << 16); }
__device__ __forceinline__ float bfhi(u32 p) { return __uint_as_float(p & 0xffff0000u); }
// split pair (v0,v1) into hi-pair hp and lo-pair lp (v0 -> low halves)
__device__ __forceinline__ void split2(float v0, float v1, u32& hp, u32& lp) {
    hp = pack_bf16(v0, v1);
    lp = pack_bf16(v0 - bflo(hp), v1 - bfhi(hp));
}

// ---------------- mma / ldmatrix ----------------
__device__ __forceinline__ void mma_bf16(float* c, const u32* a, const u32* b) {
    asm volatile(
        "mma.sync.aligned.m16n8k16.row.col.f32.bf16.bf16.f32 "
        "{%0,%1,%2,%3},{%4,%5,%6,%7},{%8,%9},{%0,%1,%2,%3};"
        : "+f"(c[0]), "+f"(c[1]), "+f"(c[2]), "+f"(c[3])
        : "r"(a[0]), "r"(a[1]), "r"(a[2]), "r"(a[3]), "r"(b[0]), "r"(b[1]));
}
__device__ __forceinline__ void ldsm4(u32* r, u32 addr) {
    asm volatile("ldmatrix.sync.aligned.m8n8.x4.shared.b16 {%0,%1,%2,%3}, [%4];"
        : "=r"(r[0]), "=r"(r[1]), "=r"(r[2]), "=r"(r[3]) : "r"(addr));
}
__device__ __forceinline__ void ldsm2(u32* r, u32 addr) {
    asm volatile("ldmatrix.sync.aligned.m8n8.x2.shared.b16 {%0,%1}, [%2];"
        : "=r"(r[0]), "=r"(r[1]) : "r"(addr));
}

__device__ float g_Mop[M_CON * D_OUT];
__device__ float g_h1[B_ROWS * H_DIM];
__device__ float g_h2[B_ROWS * H_DIM];
__device__ float g_y0[B_ROWS * D_OUT];

// ---------------------------------------------------------------------------
// Setup: Mop = inv(A A^T) @ A.   Single CTA, 256 threads.
// ---------------------------------------------------------------------------
__global__ void __launch_bounds__(256) setup_kernel(const float* __restrict__ A,
                                                    float* __restrict__ Mop) {
    __shared__ float Gs[64][65];
    __shared__ float Ks[64][65];
    __shared__ float fcol[64];
    int tid = threadIdx.x;

    for (int idx = tid; idx < 64 * 64; idx += 256) {
        int i = idx >> 6, j = idx & 63;
        float s = 0.f;
        const float* ai = A + (size_t)i * D_OUT;
        const float* aj = A + (size_t)j * D_OUT;
        #pragma unroll 8
        for (int d = 0; d < D_OUT; d++) s += ai[d] * aj[d];
        Gs[i][j] = s;
        Ks[i][j] = (i == j) ? 1.f : 0.f;
    }
    __syncthreads();

    for (int k = 0; k < 64; k++) {
        float pinv = 1.f / Gs[k][k];
        if (tid < 64) fcol[tid] = Gs[tid][k];
        __syncthreads();
        if (tid < 64) {
            Gs[k][tid] *= pinv;
            Ks[k][tid] *= pinv;
        }
        __syncthreads();
        for (int idx = tid; idx < 64 * 64; idx += 256) {
            int i = idx >> 6, j = idx & 63;
            if (i != k) {
                float f = fcol[i];
                Gs[i][j] -= f * Gs[k][j];
                Ks[i][j] -= f * Ks[k][j];
            }
        }
        __syncthreads();
    }

    for (int idx = tid; idx < 64 * D_OUT; idx += 256) {
        int m = idx >> 8, d = idx & 255;
        float s = 0.f;
        #pragma unroll 8
        for (int j = 0; j < 64; j++) s += Ks[m][j] * A[(size_t)j * D_OUT + d];
        Mop[(size_t)m * D_OUT + d] = s;
    }
}

// ---------------------------------------------------------------------------
// Trunk GEMM (unchanged best): 64x64 tile, double-buffered, reg prefetch.
// ---------------------------------------------------------------------------
__global__ void __launch_bounds__(256) gemm_kernel(const float* __restrict__ X,
                                                   const float* __restrict__ W,
                                                   const float* __restrict__ bias,
                                                   float* __restrict__ C,
                                                   int K, int N, int do_relu) {
    __shared__ float Xs[2][16][68];
    __shared__ float Ws[2][16][64];

    int tid = threadIdx.x;
    int cb = blockIdx.x * 64;
    int rb = blockIdx.y * 64;
    int ty = tid >> 4, tx = tid & 15;

    u64 acc[4][2];
    #pragma unroll
    for (int i = 0; i < 4; i++) { acc[i][0] = 0ull; acc[i][1] = 0ull; }

    int xr = tid >> 2;
    int xc = (tid & 3) * 4;
    int wr = tid >> 4;
    int wc = (tid & 15) * 4;

    const float* Xp = X + (size_t)(rb + xr) * K + xc;
    const float* Wp = W + (size_t)wr * N + cb + wc;

    float4 xv = *(const float4*)(Xp);
    float4 wv = *(const float4*)(Wp);
    Xs[0][xc + 0][xr] = xv.x;
    Xs[0][xc + 1][xr] = xv.y;
    Xs[0][xc + 2][xr] = xv.z;
    Xs[0][xc + 3][xr] = xv.w;
    *(float4*)&Ws[0][wr][wc] = wv;
    __syncthreads();

    int nk = K >> 4;
    for (int ks = 0; ks < nk - 1; ks++) {
        int p = ks & 1;
        xv = *(const float4*)(Xp + (ks + 1) * 16);
        wv = *(const float4*)(Wp + (size_t)(ks + 1) * 16 * N);
        #pragma unroll
        for (int kk = 0; kk < 16; kk++) {
            float4 a4 = *(float4*)&Xs[p][kk][ty * 4];
            ulonglong2 b = *(ulonglong2*)&Ws[p][kk][tx * 4];
            u64 a0 = pack2(a4.x, a4.x);
            u64 a1 = pack2(a4.y, a4.y);
            u64 a2 = pack2(a4.z, a4.z);
            u64 a3 = pack2(a4.w, a4.w);
            acc[0][0] = ffma2(a0, b.x, acc[0][0]); acc[0][1] = ffma2(a0, b.y, acc[0][1]);
            acc[1][0] = ffma2(a1, b.x, acc[1][0]); acc[1][1] = ffma2(a1, b.y, acc[1][1]);
            acc[2][0] = ffma2(a2, b.x, acc[2][0]); acc[2][1] = ffma2(a2, b.y, acc[2][1]);
            acc[3][0] = ffma2(a3, b.x, acc[3][0]); acc[3][1] = ffma2(a3, b.y, acc[3][1]);
        }
        int pn = p ^ 1;
        Xs[pn][xc + 0][xr] = xv.x;
        Xs[pn][xc + 1][xr] = xv.y;
        Xs[pn][xc + 2][xr] = xv.z;
        Xs[pn][xc + 3][xr] = xv.w;
        *(float4*)&Ws[pn][wr][wc] = wv;
        __syncthreads();
    }
    {
        int p = (nk - 1) & 1;
        #pragma unroll
        for (int kk = 0; kk < 16; kk++) {
            float4 a4 = *(float4*)&Xs[p][kk][ty * 4];
            ulonglong2 b = *(ulonglong2*)&Ws[p][kk][tx * 4];
            u64 a0 = pack2(a4.x, a4.x);
            u64 a1 = pack2(a4.y, a4.y);
            u64 a2 = pack2(a4.z, a4.z);
            u64 a3 = pack2(a4.w, a4.w);
            acc[0][0] = ffma2(a0, b.x, acc[0][0]); acc[0][1] = ffma2(a0, b.y, acc[0][1]);
            acc[1][0] = ffma2(a1, b.x, acc[1][0]); acc[1][1] = ffma2(a1, b.y, acc[1][1]);
            acc[2][0] = ffma2(a2, b.x, acc[2][0]); acc[2][1] = ffma2(a2, b.y, acc[2][1]);
            acc[3][0] = ffma2(a3, b.x, acc[3][0]); acc[3][1] = ffma2(a3, b.y, acc[3][1]);
        }
    }

    float4 bv = *(const float4*)(bias + cb + tx * 4);
    #pragma unroll
    for (int i = 0; i < 4; i++) {
        int row = rb + ty * 4 + i;
        float4 o;
        unpack2(acc[i][0], o.x, o.y);
        unpack2(acc[i][1], o.z, o.w);
        o.x += bv.x; o.y += bv.y; o.z += bv.z; o.w += bv.w;
        if (do_relu) {
            o.x = fmaxf(o.x, 0.f); o.y = fmaxf(o.y, 0.f);
            o.z = fmaxf(o.z, 0.f); o.w = fmaxf(o.w, 0.f);
        }
        *(float4*)(C + (size_t)row * N + cb + tx * 4) = o;
    }
}

// ---------------------------------------------------------------------------
// Tensor-core DR solver (bf16x3).
// CTA = 256 threads = 8 warps, 32 rows per CTA, grid = 128.
//
// SMEM (bytes):
//   A  hi/lo : [64][264] bf16, row stride 528  (G1 B operand, [n=m][k=d])
//   MT hi/lo : [256][72] bf16, row stride 144  (G2 B operand, Mop^T [n=d][k=m])
//   z  hi/lo : [32][264] bf16                  (G1 A operand)
//   r  hi/lo : [32][72]  bf16                  (G2 A operand; bcon in prologue)
//
// Iteration:  g = z A^T ; rm = -(0.5 g + rho0) ; p = rm Mop ;
//             u = t0 + p ; z' = 0.15 z + 1.7|u| ; final y = 0.5 z + u.
// rho0 = 0.5 y0 A^T (captured from iter-0 G1); t0 = 0.5 y0 + bcon Mop
// (computed by a prologue G2 pass). z/t0/rho0 master copies: fp32 registers
// in C-fragment layout.
// ---------------------------------------------------------------------------
#define SA_HI 0
#define SA_LO 33792
#define SM_HI 67584
#define SM_LO 104448
#define SZ_HI 141312
#define SZ_LO 158208
#define SR_HI 175104
#define SR_LO 179712
#define SOLVE_SMEM 184320

__device__ __forceinline__ void g2_block(float p[2][4][4],
                                         u32 a2h0, u32 a2h1, u32 a2l0, u32 a2l1,
                                         const u32* b2h, const u32* b2l) {
    #pragma unroll
    for (int m2 = 0; m2 < 2; m2++)
        #pragma unroll
        for (int j = 0; j < 4; j++)
            #pragma unroll
            for (int f = 0; f < 4; f++) p[m2][j][f] = 0.f;

    #pragma unroll
    for (int kk = 0; kk < 4; kk++) {
        u32 arh[2][4], arl[2][4];
        ldsm4(arh[0], a2h0 + kk * 32);
        ldsm4(arh[1], a2h1 + kk * 32);
        ldsm4(arl[0], a2l0 + kk * 32);
        ldsm4(arl[1], a2l1 + kk * 32);
        #pragma unroll
        for (int j = 0; j < 4; j++) {
            u32 bh[2], bl[2];
            ldsm2(bh, b2h[j] + kk * 32);
            ldsm2(bl, b2l[j] + kk * 32);
            #pragma unroll
            for (int m2 = 0; m2 < 2; m2++) {
                mma_bf16(p[m2][j], arh[m2], bh);
                mma_bf16(p[m2][j], arh[m2], bl);
                mma_bf16(p[m2][j], arl[m2], bh);
            }
        }
    }
}

__global__ void __launch_bounds__(256, 1) solve_kernel(
    const float* __restrict__ A, const float* __restrict__ bcon,
    const float* __restrict__ y0g, const float* __restrict__ Mop,
    const int* __restrict__ p_niter, float* __restrict__ out) {
    extern __shared__ char smem[];
    u32 sb = (u32)__cvta_generic_to_shared(smem);

    int tid = threadIdx.x;
    int lane = tid & 31, w = tid >> 5;
    int rb = blockIdx.x * 32;
    int qr = lane >> 2, qc = lane & 3;

    // ---------------- cooperative stage & convert ----------------
    // A [64][256] -> SA (hi/lo)
    for (int i = tid; i < 64 * 128; i += 256) {
        int row = i >> 7, cp = i & 127;
        float2 v = ((const float2*)A)[i];
        u32 hp, lp; split2(v.x, v.y, hp, lp);
        *(u32*)(smem + SA_HI + row * 528 + cp * 4) = hp;
        *(u32*)(smem + SA_LO + row * 528 + cp * 4) = lp;
    }
    // Mop [64][256] -> transposed SM [256][72] (hi/lo)
    for (int i = tid; i < 64 * 128; i += 256) {
        int m = i >> 7, cp = i & 127;
        float2 v = ((const float2*)Mop)[i];
        int d0 = cp * 2;
        u32 hp, lp; split2(v.x, v.y, hp, lp);
        *(unsigned short*)(smem + SM_HI + d0 * 144 + m * 2)       = (unsigned short)(hp & 0xffff);
        *(unsigned short*)(smem + SM_HI + (d0 + 1) * 144 + m * 2) = (unsigned short)(hp >> 16);
        *(unsigned short*)(smem + SM_LO + d0 * 144 + m * 2)       = (unsigned short)(lp & 0xffff);
        *(unsigned short*)(smem + SM_LO + (d0 + 1) * 144 + m * 2) = (unsigned short)(lp >> 16);
    }
    // z init = y0 block [32][256] -> SZ (hi/lo)
    {
        const float2* yb = (const float2*)(y0g + (size_t)rb * D_OUT);
        for (int i = tid; i < 32 * 128; i += 256) {
            int row = i >> 7, cp = i & 127;
            float2 v = yb[i];
            u32 hp, lp; split2(v.x, v.y, hp, lp);
            *(u32*)(smem + SZ_HI + row * 528 + cp * 4) = hp;
            *(u32*)(smem + SZ_LO + row * 528 + cp * 4) = lp;
        }
    }
    // bcon block [32][64] -> SR (hi/lo)   (prologue G2 input)
    {
        const float2* bb = (const float2*)(bcon + (size_t)rb * M_CON);
        for (int i = tid; i < 32 * 32; i += 256) {
            int row = i >> 5, cp = i & 31;
            float2 v = bb[i];
            u32 hp, lp; split2(v.x, v.y, hp, lp);
            *(u32*)(smem + SR_HI + row * 144 + cp * 4) = hp;
            *(u32*)(smem + SR_LO + row * 144 + cp * 4) = lp;
        }
    }
    __syncthreads();

    // ---------------- fragment address bases ----------------
    int l7 = lane & 7, g8 = (lane >> 3) & 1, g16 = (lane >> 4) & 1;
    int lx = lane & 15, lx7 = lx & 7, lx8 = (lx >> 3) & 1;

    // G1: m-tile and 2 n-tiles per warp
    int mt  = w & 1;
    int ntb = (w >> 1) * 2;
    u32 a1h = sb + SZ_HI + (u32)((mt * 16 + l7 + g8 * 8) * 528 + g16 * 16);
    u32 a1l = a1h + (SZ_LO - SZ_HI);
    u32 b1h[2], b1l[2];
    #pragma unroll
    for (int t = 0; t < 2; t++) {
        b1h[t] = sb + SA_HI + (u32)(((ntb + t) * 8 + lx7) * 528 + lx8 * 16);
        b1l[t] = b1h[t] + (SA_LO - SA_HI);
    }

    // G2: 2 m-tiles x 4 n-tiles per warp (n-range [w*32, w*32+32))
    u32 a2h0 = sb + SR_HI + (u32)((0 * 16 + l7 + g8 * 8) * 144 + g16 * 16);
    u32 a2h1 = sb + SR_HI + (u32)((1 * 16 + l7 + g8 * 8) * 144 + g16 * 16);
    u32 a2l0 = a2h0 + (SR_LO - SR_HI);
    u32 a2l1 = a2h1 + (SR_LO - SR_HI);
    u32 b2h[4], b2l[4];
    #pragma unroll
    for (int j = 0; j < 4; j++) {
        b2h[j] = sb + SM_HI + (u32)(((w * 4 + j) * 8 + lx7) * 144 + lx8 * 16);
        b2l[j] = b2h[j] + (SM_LO - SM_HI);
    }

    // ---------------- prologue: c = bcon @ Mop ; t0, z regs ----------------
    float t0r[2][4][4], zf[2][4][4], rho0[2][4];
    {
        float c[2][4][4];
        g2_block(c, a2h0, a2h1, a2l0, a2l1, b2h, b2l);
        #pragma unroll
        for (int m2 = 0; m2 < 2; m2++) {
            int r0 = rb + m2 * 16 + qr;
            #pragma unroll
            for (int j = 0; j < 4; j++) {
                int col = w * 32 + j * 8 + qc * 2;
                float2 ya = *(const float2*)(y0g + (size_t)r0 * D_OUT + col);
                float2 yb = *(const float2*)(y0g + (size_t)(r0 + 8) * D_OUT + col);
                t0r[m2][j][0] = 0.5f * ya.x + c[m2][j][0];
                t0r[m2][j][1] = 0.5f * ya.y + c[m2][j][1];
                t0r[m2][j][2] = 0.5f * yb.x + c[m2][j][2];
                t0r[m2][j][3] = 0.5f * yb.y + c[m2][j][3];
                zf[m2][j][0] = ya.x; zf[m2][j][1] = ya.y;
                zf[m2][j][2] = yb.x; zf[m2][j][3] = yb.y;
            }
        }
    }
    __syncthreads();   // bcon staging now free for r

    int niter = *p_niter;
    if (niter <= 0) {
        #pragma unroll
        for (int m2 = 0; m2 < 2; m2++) {
            int r0 = rb + m2 * 16 + qr;
            #pragma unroll
            for (int j = 0; j < 4; j++) {
                int col = w * 32 + j * 8 + qc * 2;
                *(float2*)(out + (size_t)r0 * D_OUT + col)       = make_float2(zf[m2][j][0], zf[m2][j][1]);
                *(float2*)(out + (size_t)(r0 + 8) * D_OUT + col) = make_float2(zf[m2][j][2], zf[m2][j][3]);
            }
        }
        return;
    }

    const float zk = 1.0f - OMEGA_F * 0.5f;   // 0.15

    // pw1 store offsets (G1 C layout -> r staging)
    int rrow0 = mt * 16 + qr;
    int rrow1 = rrow0 + 8;

    for (int it = 0; it < niter; it++) {
        // ---------------- G1: g = z A^T ----------------
        float cg[2][4];
        #pragma unroll
        for (int t = 0; t < 2; t++)
            #pragma unroll
            for (int f = 0; f < 4; f++) cg[t][f] = 0.f;

        #pragma unroll
        for (int kk = 0; kk < 16; kk++) {
            u32 azh[4], azl[4];
            ldsm4(azh, a1h + kk * 32);
            ldsm4(azl, a1l + kk * 32);
            #pragma unroll
            for (int t = 0; t < 2; t++) {
                u32 bh[2], bl[2];
                ldsm2(bh, b1h[t] + kk * 32);
                ldsm2(bl, b1l[t] + kk * 32);
                mma_bf16(cg[t], azh, bh);
                mma_bf16(cg[t], azh, bl);
                mma_bf16(cg[t], azl, bh);
            }
        }

        // ---------------- pw1: rm = -(0.5 g + rho0) -> r staging ----------------
        if (it == 0) {
            #pragma unroll
            for (int t = 0; t < 2; t++)
                #pragma unroll
                for (int f = 0; f < 4; f++) rho0[t][f] = 0.5f * cg[t][f];
        }
        #pragma unroll
        for (int t = 0; t < 2; t++) {
            int col = (ntb + t) * 8 + qc * 2;
            float rm0 = -(0.5f * cg[t][0] + rho0[t][0]);
            float rm1 = -(0.5f * cg[t][1] + rho0[t][1]);
            float rm2 = -(0.5f * cg[t][2] + rho0[t][2]);
            float rm3 = -(0.5f * cg[t][3] + rho0[t][3]);
            u32 hp, lp;
            split2(rm0, rm1, hp, lp);
            *(u32*)(smem + SR_HI + rrow0 * 144 + col * 2) = hp;
            *(u32*)(smem + SR_LO + rrow0 * 144 + col * 2) = lp;
            split2(rm2, rm3, hp, lp);
            *(u32*)(smem + SR_HI + rrow1 * 144 + col * 2) = hp;
            *(u32*)(smem + SR_LO + rrow1 * 144 + col * 2) = lp;
        }
        __syncthreads();

        // ---------------- G2: p = rm Mop ----------------
        float p[2][4][4];
        g2_block(p, a2h0, a2h1, a2l0, a2l1, b2h, b2l);

        // ---------------- pw2: u = t0 + p ; z / out update ----------------
        bool last = (it == niter - 1);
        #pragma unroll
        for (int m2 = 0; m2 < 2; m2++) {
            int row0 = m2 * 16 + qr;
            int row1 = row0 + 8;
            #pragma unroll
            for (int j = 0; j < 4; j++) {
                int col = w * 32 + j * 8 + qc * 2;
                float u0 = t0r[m2][j][0] + p[m2][j][0];
                float u1 = t0r[m2][j][1] + p[m2][j][1];
                float u2 = t0r[m2][j][2] + p[m2][j][2];
                float u3 = t0r[m2][j][3] + p[m2][j][3];
                if (last) {
                    *(float2*)(out + (size_t)(rb + row0) * D_OUT + col) =
                        make_float2(0.5f * zf[m2][j][0] + u0, 0.5f * zf[m2][j][1] + u1);
                    *(float2*)(out + (size_t)(rb + row1) * D_OUT + col) =
                        make_float2(0.5f * zf[m2][j][2] + u2, 0.5f * zf[m2][j][3] + u3);
                } else {
                    zf[m2][j][0] = zk * zf[m2][j][0] + OMEGA_F * fabsf(u0);
                    zf[m2][j][1] = zk * zf[m2][j][1] + OMEGA_F * fabsf(u1);
                    zf[m2][j][2] = zk * zf[m2][j][2] + OMEGA_F * fabsf(u2);
                    zf[m2][j][3] = zk * zf[m2][j][3] + OMEGA_F * fabsf(u3);
                    u32 hp, lp;
                    split2(zf[m2][j][0], zf[m2][j][1], hp, lp);
                    *(u32*)(smem + SZ_HI + row0 * 528 + col * 2) = hp;
                    *(u32*)(smem + SZ_LO + row0 * 528 + col * 2) = lp;
                    split2(zf[m2][j][2], zf[m2][j][3], hp, lp);
                    *(u32*)(smem + SZ_HI + row1 * 528 + col * 2) = hp;
                    *(u32*)(smem + SZ_LO + row1 * 528 + col * 2) = lp;
                }
            }
        }
        __syncthreads();
    }
}

// ---------------------------------------------------------------------------
extern "C" void kernel_launch(void* const* d_in, const int* in_sizes, int n_in,
                              void* d_out, int out_size) {
    const float* x    = (const float*)d_in[0];
    const float* bcon = (const float*)d_in[1];
    const float* A    = (const float*)d_in[2];
    const float* W1   = (const float*)d_in[3];
    const float* b1   = (const float*)d_in[4];
    const float* W2   = (const float*)d_in[5];
    const float* b2   = (const float*)d_in[6];
    const float* W3   = (const float*)d_in[7];
    const float* b3   = (const float*)d_in[8];
    const float* Wout = (const float*)d_in[9];
    const float* bout = (const float*)d_in[10];
    const int*   nit  = (const int*)d_in[11];
    float* out = (float*)d_out;

    float *p_Mop, *p_h1, *p_h2, *p_y0;
    cudaGetSymbolAddress((void**)&p_Mop, g_Mop);
    cudaGetSymbolAddress((void**)&p_h1, g_h1);
    cudaGetSymbolAddress((void**)&p_h2, g_h2);
    cudaGetSymbolAddress((void**)&p_y0, g_y0);

    gemm_kernel<<<dim3(H_DIM / 64, B_ROWS / 64), 256>>>(x,    W1,   b1,   p_h1, D_INF, H_DIM, 1);
    gemm_kernel<<<dim3(H_DIM / 64, B_ROWS / 64), 256>>>(p_h1, W2,   b2,   p_h2, H_DIM, H_DIM, 1);
    gemm_kernel<<<dim3(H_DIM / 64, B_ROWS / 64), 256>>>(p_h2, W3,   b3,   p_h1, H_DIM, H_DIM, 1);
    gemm_kernel<<<dim3(D_OUT / 64, B_ROWS / 64), 256>>>(p_h1, Wout, bout, p_y0, H_DIM, D_OUT, 0);

    setup_kernel<<<1, 256>>>(A, p_Mop);

    cudaFuncSetAttribute(solve_kernel, cudaFuncAttributeMaxDynamicSharedMemorySize, SOLVE_SMEM);
    solve_kernel<<<B_ROWS / 32, 256, SOLVE_SMEM>>>(A, bcon, p_y0, p_Mop, nit, out);
}